// round 2
// baseline (speedup 1.0000x reference)
#include <cuda_runtime.h>
#include <math.h>

#define D_     32
#define H_     56
#define W_     56
#define HW     3136        // 56*56
#define P_     100352      // 32*56*56
#define CIN    64
#define HID    128
#define DIN    256
#define NST    16
#define L_     32

// ---------------- scratch (static device memory; no allocs allowed) --------
__device__ float g_x   [2 * 256 * P_];        // pointwise-conv output (2,256,D,H,W)
__device__ float g_xc  [2 * 256 * P_];        // depthwise-conv output
__device__ float g_x1r [2 * 128 * P_];        // relu(dense conv) of x1 half
__device__ float g_wt  [27 * 128 * 128];      // W_s transposed to [tap][c][o]
__device__ float g_t0  [2 * 128 * L_];        // pooled x2: [b][c][d]
__device__ float g_gate[2 * 128 * L_];        // sigmoid gate: [b][o][l]

// ---------------- K0: transpose dense-conv weights to [tap][c][o] ----------
__global__ void k_wt(const float* __restrict__ Ws) {
    int i = blockIdx.x * 256 + threadIdx.x;
    if (i >= 27 * 128 * 128) return;
    int tap = i / (128 * 128);
    int r   = i % (128 * 128);
    int c   = r / 128;
    int o   = r % 128;
    g_wt[i] = Ws[(o * 128 + c) * 27 + tap];
}

// ---------------- K1: pointwise conv 64 -> 256 -----------------------------
// grid (784, 2), 256 thr. smem: Wsh transposed [c][256] (64KB) + Ish [64][128] (32KB)
__global__ void __launch_bounds__(256) k_pw(const float* __restrict__ inp,
                                            const float* __restrict__ Win) {
    extern __shared__ float sm[];
    float* Wsh = sm;            // 16384 floats: [c*256 + o]
    float* Ish = sm + 16384;    //  8192 floats: [c*128 + p]
    int b  = blockIdx.y;
    int p0 = blockIdx.x * 128;
    int tid = threadIdx.x;
    for (int i = tid; i < 16384; i += 256) {
        int o = i >> 6, c = i & 63;
        Wsh[c * 256 + o] = Win[i];
    }
    for (int i = tid; i < 8192; i += 256) {
        int c = i >> 7, p = i & 127;
        Ish[i] = inp[(size_t)(b * 64 + c) * P_ + p0 + p];
    }
    __syncthreads();
    int p  = tid & 127;
    int oh = tid >> 7;              // 0..1
    for (int og = 0; og < 32; og++) {
        int ob = og * 8 + oh * 4;
        float a0 = 0.f, a1 = 0.f, a2 = 0.f, a3 = 0.f;
        #pragma unroll 16
        for (int c = 0; c < 64; c++) {
            float  xv = Ish[c * 128 + p];
            float4 wv = *(const float4*)&Wsh[c * 256 + ob];
            a0 += wv.x * xv; a1 += wv.y * xv; a2 += wv.z * xv; a3 += wv.w * xv;
        }
        size_t base = (size_t)(b * 256) * P_ + p0 + p;
        g_x[base + (size_t)(ob + 0) * P_] = a0;
        g_x[base + (size_t)(ob + 1) * P_] = a1;
        g_x[base + (size_t)(ob + 2) * P_] = a2;
        g_x[base + (size_t)(ob + 3) * P_] = a3;
    }
}

// ---------------- K2: depthwise 3x3x3, SAME, groups=256 --------------------
// grid (D*H=1792, 256, 2), 64 thr (w)
__global__ void k_dw(const float* __restrict__ Wdw) {
    int b = blockIdx.z, c = blockIdx.y;
    int dh = blockIdx.x;
    int d = dh / 56, h = dh % 56;
    int w = threadIdx.x;
    if (w >= 56) return;
    const float* wg  = &Wdw[c * 27];
    const float* src = &g_x[(size_t)(b * 256 + c) * P_];
    float acc = 0.f;
    #pragma unroll
    for (int kd = 0; kd < 3; kd++) {
        int dd = d + kd - 1;
        if (dd < 0 || dd >= D_) continue;
        #pragma unroll
        for (int kh = 0; kh < 3; kh++) {
            int hh = h + kh - 1;
            if (hh < 0 || hh >= 56) continue;
            const float* row = &src[dd * HW + hh * 56];
            #pragma unroll
            for (int kw = 0; kw < 3; kw++) {
                int ww = w + kw - 1;
                if (ww < 0 || ww >= 56) continue;
                acc += wg[kd * 9 + kh * 3 + kw] * row[ww];
            }
        }
    }
    g_xc[(size_t)(b * 256 + c) * P_ + d * HW + h * 56 + w] = acc;
}

// ---------------- K3: dense 3x3x3 conv 128->128 + relu (the hot kernel) ----
// grid (28, 32, 2): block = (b, d, h0..h0+1) x all o x all w. 256 thr, 184KB smem.
__global__ void __launch_bounds__(256, 1) k_conv() {
    extern __shared__ float sm[];
    float* Ish = sm;            // 4*128*58 = 29696 floats: [row][c][wp]
    float* Wsh = sm + 29696;    // 16384 floats: [c*128 + o]
    int b  = blockIdx.z;
    int d  = blockIdx.y;
    int h0 = blockIdx.x * 2;
    int tid = threadIdx.x;
    int og  = tid & 31;         // o group: o = og*4 + oi
    int grp = tid >> 5;         // w group: w = grp*7 + wi
    int ob  = og * 4;
    int wb  = grp * 7;

    float acc[56];
    #pragma unroll
    for (int i = 0; i < 56; i++) acc[i] = 0.f;

    for (int kd = 0; kd < 3; kd++) {
        int dd = d + kd - 1;
        __syncthreads();   // previous tap finished reading Ish
        for (int i = tid; i < 29696; i += 256) {
            int r   = i / 7424;          // 128*58
            int rem = i % 7424;
            int c   = rem / 58;
            int wp  = rem % 58;
            int hh  = h0 - 1 + r;
            int w   = wp - 1;
            float v = 0.f;
            if (dd >= 0 && dd < D_ && hh >= 0 && hh < 56 && (unsigned)w < 56u)
                v = g_xc[((size_t)(b * 256 + c) * D_ + dd) * HW + hh * 56 + w];
            Ish[i] = v;
        }
        for (int kh = 0; kh < 3; kh++)
        for (int kw = 0; kw < 3; kw++) {
            int tap = (kd * 3 + kh) * 3 + kw;
            __syncthreads();   // Ish stores visible / previous Wsh reads done
            for (int i = tid; i < 16384; i += 256)
                Wsh[i] = g_wt[tap * 16384 + i];
            __syncthreads();
            #pragma unroll 8
            for (int c = 0; c < 128; c++) {
                float4 wv = *(const float4*)&Wsh[c * 128 + ob];
                #pragma unroll
                for (int hh2 = 0; hh2 < 2; hh2++) {
                    const float* row = &Ish[((hh2 + kh) * 128 + c) * 58 + wb + kw];
                    #pragma unroll
                    for (int wi = 0; wi < 7; wi++) {
                        float xv = row[wi];
                        int a = (hh2 * 7 + wi) * 4;
                        acc[a + 0] += wv.x * xv;
                        acc[a + 1] += wv.y * xv;
                        acc[a + 2] += wv.z * xv;
                        acc[a + 3] += wv.w * xv;
                    }
                }
            }
        }
    }
    // stage through smem for coalesced stores, apply relu
    __syncthreads();
    float* S = sm;   // 128*2*56 = 14336 floats
    #pragma unroll
    for (int hh2 = 0; hh2 < 2; hh2++)
        #pragma unroll
        for (int wi = 0; wi < 7; wi++)
            #pragma unroll
            for (int oi = 0; oi < 4; oi++)
                S[((ob + oi) * 2 + hh2) * 56 + wb + wi] =
                    fmaxf(acc[(hh2 * 7 + wi) * 4 + oi], 0.f);
    __syncthreads();
    for (int i = tid; i < 14336; i += 256) {
        int o   = i / 112;
        int rem = i % 112;
        int hh2 = rem / 56;
        int w   = rem % 56;
        g_x1r[((size_t)(b * 128 + o) * D_ + d) * HW + (h0 + hh2) * 56 + w] = S[i];
    }
}

// ---------------- K4: global HxW mean of x2 half ---------------------------
// grid 8192 = b*128*32 blocks, 256 thr
__global__ void k_pool() {
    int idx = blockIdx.x;
    int b = idx / (128 * L_);
    int rem = idx % (128 * L_);
    int c = rem / L_, d = rem % L_;
    const float* src = &g_xc[((size_t)(b * 256 + 128 + c) * D_ + d) * HW];
    float s = 0.f;
    for (int i = threadIdx.x; i < HW; i += 256) s += src[i];
    __shared__ float red[256];
    red[threadIdx.x] = s;
    __syncthreads();
    for (int st = 128; st > 0; st >>= 1) {
        if (threadIdx.x < st) red[threadIdx.x] += red[threadIdx.x + st];
        __syncthreads();
    }
    if (threadIdx.x == 0)
        g_t0[(b * 128 + c) * L_ + d] = red[0] * (1.f / 3136.f);
}

// ---------------- K6: W_t1 + full Mamba + W_t2 + sigmoid (fused) -----------
// grid 2 (batch), 256 thr, 169KB dyn smem
__global__ void __launch_bounds__(256) k_mamba(
        const float* __restrict__ Wt1,   const float* __restrict__ min_w,
        const float* __restrict__ cw,    const float* __restrict__ cb,
        const float* __restrict__ mx_w,  const float* __restrict__ mdt_w,
        const float* __restrict__ mdt_b, const float* __restrict__ A_log,
        const float* __restrict__ Dp,    const float* __restrict__ mout_w,
        const float* __restrict__ Wt2) {
    extern __shared__ float sm[];
    float* t0s = sm;           // 4096  [c*32 + l]
    float* seq = sm + 4096;    // 4096  [l*128 + h]
    float* xb  = sm + 8192;    // 8192  [l*256 + d]  (later reused as ys)
    float* zb  = sm + 16384;   // 8192
    float* xcv = sm + 24576;   // 8192
    float* dtb = sm + 32768;   // 8192  (later reused as yo [l*128+h])
    float* prb = sm + 40960;   // 1280  [l*40 + j]
    int b = blockIdx.x, tid = threadIdx.x;

    for (int i = tid; i < 4096; i += 256) t0s[i] = g_t0[b * 4096 + i];
    __syncthreads();
    // seq[l][h] = sum_c Wt1[h][c] * t0s[c][l]
    for (int i = tid; i < 4096; i += 256) {
        int l = i >> 7, h = i & 127;
        float a = 0.f;
        for (int c = 0; c < 128; c++) a += Wt1[h * 128 + c] * t0s[c * L_ + l];
        seq[i] = a;
    }
    __syncthreads();
    // xz = seq @ m_in_w.T
    for (int i = tid; i < 16384; i += 256) {
        int l = i >> 9, j = i & 511;
        float a = 0.f;
        const float* wr = &min_w[j * 128];
        for (int h = 0; h < 128; h++) a += wr[h] * seq[l * 128 + h];
        if (j < 256) xb[l * 256 + j] = a;
        else         zb[l * 256 + (j - 256)] = a;
    }
    __syncthreads();
    // causal depthwise conv1d (K=4) + bias + silu
    for (int i = tid; i < 8192; i += 256) {
        int l = i >> 8, dch = i & 255;
        float a = cb[dch];
        #pragma unroll
        for (int k = 0; k < 4; k++) {
            int ll = l - 3 + k;
            if (ll >= 0) a += xb[ll * 256 + dch] * cw[dch * 4 + k];
        }
        xcv[i] = a / (1.f + expf(-a));
    }
    __syncthreads();
    // x_proj: prb[l][0:8]=dt_raw, [8:24]=B, [24:40]=C
    for (int i = tid; i < 1280; i += 256) {
        int l = i / 40, j = i % 40;
        float a = 0.f;
        const float* wr = &mx_w[j * 256];
        for (int dd = 0; dd < 256; dd++) a += wr[dd] * xcv[l * 256 + dd];
        prb[i] = a;
    }
    __syncthreads();
    // dt = softplus(dt_raw @ dt_w.T + dt_b)
    for (int i = tid; i < 8192; i += 256) {
        int l = i >> 8, dch = i & 255;
        float a = mdt_b[dch];
        const float* wr = &mdt_w[dch * 8];
        #pragma unroll
        for (int r = 0; r < 8; r++) a += wr[r] * prb[l * 40 + r];
        dtb[i] = (a > 20.f) ? a : log1pf(expf(a));
    }
    __syncthreads();
    // selective scan: thread tid owns channel dch = tid
    {
        int dch = tid;
        float A[NST], hst[NST];
        #pragma unroll
        for (int n = 0; n < NST; n++) {
            A[n]   = -expf(A_log[dch * NST + n]);
            hst[n] = 0.f;
        }
        float Dv = Dp[dch];
        for (int l = 0; l < L_; l++) {
            float dtv = dtb[l * 256 + dch];
            float xv  = xcv[l * 256 + dch];
            float y = 0.f;
            #pragma unroll
            for (int n = 0; n < NST; n++) {
                float dA = __expf(dtv * A[n]);
                hst[n] = dA * hst[n] + dtv * prb[l * 40 + 8 + n] * xv;
                y += hst[n] * prb[l * 40 + 24 + n];
            }
            y += xv * Dv;
            float zv = zb[l * 256 + dch];
            xb[l * 256 + dch] = y * (zv / (1.f + expf(-zv)));  // ys
        }
    }
    __syncthreads();
    // yo = ys @ m_out_w.T  (reuse dtb)
    for (int i = tid; i < 4096; i += 256) {
        int l = i >> 7, h = i & 127;
        float a = 0.f;
        const float* wr = &mout_w[h * 256];
        for (int dd = 0; dd < 256; dd++) a += wr[dd] * xb[l * 256 + dd];
        dtb[i] = a;
    }
    __syncthreads();
    // gate[o][l] = sigmoid(sum_c Wt2[o][c] * yo[l][c])
    for (int i = tid; i < 4096; i += 256) {
        int o = i >> 5, l = i & 31;
        float a = 0.f;
        const float* wr = &Wt2[o * 128];
        for (int c = 0; c < 128; c++) a += wr[c] * dtb[l * 128 + c];
        g_gate[b * 4096 + o * L_ + l] = 1.f / (1.f + expf(-a));
    }
}

// ---------------- K7: out = W_out @ (x1r * gate) ---------------------------
// grid (784, 2), 256 thr, 96KB smem
__global__ void __launch_bounds__(256) k_out(const float* __restrict__ Wout,
                                             float* __restrict__ out) {
    extern __shared__ float sm[];
    float* Xsh = sm;           // 128*128 = 16384: [c*128 + p]
    float* Wsh = sm + 16384;   // 128*64  =  8192: [c*64 + o]
    int b  = blockIdx.y;
    int p0 = blockIdx.x * 128;
    int tid = threadIdx.x;
    for (int i = tid; i < 8192; i += 256) {
        int o = i >> 7, c = i & 127;
        Wsh[c * 64 + o] = Wout[i];
    }
    for (int i = tid; i < 16384; i += 256) {
        int c = i >> 7, p = i & 127;
        int gp = p0 + p;
        int d  = gp / HW;
        Xsh[i] = g_x1r[(size_t)(b * 128 + c) * P_ + gp] *
                 g_gate[b * 4096 + c * L_ + d];
    }
    __syncthreads();
    int lane = tid & 31;
    int ocb  = (tid >> 5) * 8;
    float acc[4][8];
    #pragma unroll
    for (int j = 0; j < 4; j++)
        #pragma unroll
        for (int oi = 0; oi < 8; oi++) acc[j][oi] = 0.f;
    #pragma unroll 4
    for (int c = 0; c < 128; c++) {
        float xv[4];
        #pragma unroll
        for (int j = 0; j < 4; j++) xv[j] = Xsh[c * 128 + lane + j * 32];
        float4 wa = *(const float4*)&Wsh[c * 64 + ocb];
        float4 wb2 = *(const float4*)&Wsh[c * 64 + ocb + 4];
        float wv[8] = {wa.x, wa.y, wa.z, wa.w, wb2.x, wb2.y, wb2.z, wb2.w};
        #pragma unroll
        for (int j = 0; j < 4; j++)
            #pragma unroll
            for (int oi = 0; oi < 8; oi++)
                acc[j][oi] += wv[oi] * xv[j];
    }
    #pragma unroll
    for (int oi = 0; oi < 8; oi++)
        #pragma unroll
        for (int j = 0; j < 4; j++)
            out[(size_t)(b * 64 + ocb + oi) * P_ + p0 + lane + j * 32] = acc[j][oi];
}

// ---------------- launch ---------------------------------------------------
extern "C" void kernel_launch(void* const* d_in, const int* in_sizes, int n_in,
                              void* d_out, int out_size) {
    const float* inp    = (const float*)d_in[0];
    const float* W_in   = (const float*)d_in[1];
    const float* W_dw   = (const float*)d_in[2];
    const float* W_s    = (const float*)d_in[3];
    const float* W_t1   = (const float*)d_in[4];
    const float* W_t2   = (const float*)d_in[5];
    const float* m_in_w = (const float*)d_in[6];
    const float* m_cw   = (const float*)d_in[7];
    const float* m_cb   = (const float*)d_in[8];
    const float* m_x_w  = (const float*)d_in[9];
    const float* m_dt_w = (const float*)d_in[10];
    const float* m_dt_b = (const float*)d_in[11];
    const float* m_Alog = (const float*)d_in[12];
    const float* m_D    = (const float*)d_in[13];
    const float* m_ow   = (const float*)d_in[14];
    const float* W_out  = (const float*)d_in[15];

    cudaFuncSetAttribute(k_pw,    cudaFuncAttributeMaxDynamicSharedMemorySize, 98304);
    cudaFuncSetAttribute(k_conv,  cudaFuncAttributeMaxDynamicSharedMemorySize, 184320);
    cudaFuncSetAttribute(k_mamba, cudaFuncAttributeMaxDynamicSharedMemorySize, 168960);
    cudaFuncSetAttribute(k_out,   cudaFuncAttributeMaxDynamicSharedMemorySize, 98304);

    k_wt<<<(27 * 128 * 128 + 255) / 256, 256>>>(W_s);
    k_pw<<<dim3(P_ / 128, 2), 256, 98304>>>(inp, W_in);
    k_dw<<<dim3(D_ * H_, 256, 2), 64>>>(W_dw);
    k_conv<<<dim3(28, D_, 2), 256, 184320>>>();
    k_pool<<<2 * 128 * L_, 256>>>();
    k_mamba<<<2, 256, 168960>>>(W_t1, m_in_w, m_cw, m_cb, m_x_w, m_dt_w, m_dt_b,
                                m_Alog, m_D, m_ow, W_t2);
    k_out<<<dim3(P_ / 128, 2), 256, 98304>>>(W_out, (float*)d_out);
}